// round 14
// baseline (speedup 1.0000x reference)
#include <cuda_runtime.h>
#include <cuda_fp16.h>
#include <mma.h>
#include <cstdint>

using namespace nvcuda;

#define NB 512
#define NL 100
#define ND 1024
#define M_TOTAL (NB * NL)   // 51200
#define M_PAD (M_TOTAL + 128)

// ---- scratch (static device arrays; no cudaMalloc allowed) ----
__device__ float  g_docs[NB * ND];
__device__ float  g_docvec[NB * ND];
__device__ float  g_cwu[NB * ND];                 // content_w + sal_w @ doc_vec
__device__ float  g_hWn[(size_t)NB * NL * ND];    // compact hWn
__device__ __half g_bhi[ND * ND];                 // nov_w fp16 hi ([k][n])
__device__ __half g_blo[ND * ND];                 // nov_w fp16 lo
__device__ __half g_ahi[(size_t)M_PAD * ND];      // compact sent fp16 hi
__device__ __half g_alo[(size_t)M_PAD * ND];      // compact sent fp16 lo
__device__ float  g_absp[NL];
__device__ float  g_relpv[10];
__device__ int    g_rowidx[M_PAD];
__device__ int    g_off[NB];
__device__ int    g_mcnt[1];

// ============================================================
// K0: prefix-sum of doc_lens -> offsets + compact row index map
// ============================================================
__global__ void k_prefix(const int* __restrict__ lens) {
    __shared__ int sh[NB];
    int t = threadIdx.x;
    int len = lens[t];
    sh[t] = len;
    __syncthreads();
    for (int off = 1; off < NB; off <<= 1) {
        int add = (t >= off) ? sh[t - off] : 0;
        __syncthreads();
        sh[t] += add;
        __syncthreads();
    }
    int off_b = sh[t] - len;
    g_off[t] = off_b;
    for (int l = 0; l < len; l++) g_rowidx[off_b + l] = t * NL + l;
    if (t == NB - 1) {
        int total = sh[t];
        g_mcnt[0] = total;
        int pad = ((total + 127) / 128) * 128;
        for (int i = total; i < pad; i++) g_rowidx[i] = 0;
    }
}

// ============================================================
// K0b: pre-split compact A rows into fp16 hi/lo (block = one compact row)
// ============================================================
__global__ void __launch_bounds__(256) k_splitA(const float* __restrict__ sent,
                                                __half* __restrict__ ah,
                                                __half* __restrict__ al) {
    int m = blockIdx.x;
    int pad = (g_mcnt[0] + 127) & ~127;
    if (m >= pad) return;
    int src = g_rowidx[m];
    const float4* p = (const float4*)(sent + (size_t)src * ND);
    int t = threadIdx.x;
    float4 v = p[t];
    __half h0 = __float2half_rn(v.x), h1 = __float2half_rn(v.y);
    __half h2 = __float2half_rn(v.z), h3 = __float2half_rn(v.w);
    __half l0 = __float2half_rn(v.x - __half2float(h0));
    __half l1 = __float2half_rn(v.y - __half2float(h1));
    __half l2 = __float2half_rn(v.z - __half2float(h2));
    __half l3 = __float2half_rn(v.w - __half2float(h3));
    __half2* ph = (__half2*)(ah + (size_t)m * ND) + 2 * t;
    __half2* pl = (__half2*)(al + (size_t)m * ND) + 2 * t;
    ph[0] = __halves2half2(h0, h1); ph[1] = __halves2half2(h2, h3);
    pl[0] = __halves2half2(l0, l1); pl[1] = __halves2half2(l2, l3);
}

// ============================================================
// K1: docs[b,d] = sum_{l<len} sent[b,l,d] / len  (float4, block per b)
// ============================================================
__global__ void __launch_bounds__(256) k_docs(const float* __restrict__ sent,
                                              const int* __restrict__ lens) {
    int b = blockIdx.x;
    int t = threadIdx.x;                       // 256 threads x float4 = 1024 d
    int len = lens[b];
    const float4* p = (const float4*)(sent + (size_t)b * NL * ND) + t;
    float4 s = make_float4(0.f, 0.f, 0.f, 0.f);
    for (int l = 0; l < len; l++) {
        float4 v = p[(size_t)l * (ND / 4)];
        s.x += v.x; s.y += v.y; s.z += v.z; s.w += v.w;
    }
    float inv = 1.f / (float)len;
    s.x *= inv; s.y *= inv; s.z *= inv; s.w *= inv;
    ((float4*)g_docs)[b * (ND / 4) + t] = s;
}

// ============================================================
// K2: abs_p / rel_pv dot products
// ============================================================
__global__ void k_pos(const float* __restrict__ abs_emb, const float* __restrict__ rel_emb,
                      const float* __restrict__ abs_w, const float* __restrict__ rel_w) {
    int t = threadIdx.x;
    if (t < NL) {
        float s = 0.f;
        for (int j = 0; j < 50; j++) s += abs_emb[t * 50 + j] * abs_w[j];
        g_absp[t] = s;
    } else if (t >= 100 && t < 110) {
        int i = t - 100;
        float s = 0.f;
        for (int j = 0; j < 50; j++) s += rel_emb[i * 50 + j] * rel_w[j];
        g_relpv[i] = s;
    }
}

// ============================================================
// K3: fp16 split of nov_w ([k][n] row-major)
// ============================================================
__global__ void k_splitB(const float* __restrict__ w, __half* __restrict__ bh,
                         __half* __restrict__ bl) {
    int i = blockIdx.x * blockDim.x + threadIdx.x;
    float4 v = ((const float4*)w)[i];
    __half h0 = __float2half_rn(v.x), h1 = __float2half_rn(v.y);
    __half h2 = __float2half_rn(v.z), h3 = __float2half_rn(v.w);
    __half l0 = __float2half_rn(v.x - __half2float(h0));
    __half l1 = __float2half_rn(v.y - __half2float(h1));
    __half l2 = __float2half_rn(v.z - __half2float(h2));
    __half l3 = __float2half_rn(v.w - __half2float(h3));
    ((__half2*)bh)[2 * i] = __halves2half2(h0, h1);
    ((__half2*)bh)[2 * i + 1] = __halves2half2(h2, h3);
    ((__half2*)bl)[2 * i] = __halves2half2(l0, l1);
    ((__half2*)bl)[2 * i + 1] = __halves2half2(l2, l3);
}

// ============================================================
// K4/K5: NT GEMM via wmma fp16 3-term split, in-kernel splitting.
// CTA tile 64(M) x 64(N), BK=32, 8 warps (warp tile 16x32), grid 128.
// W is [n][k] row-major -> col_major wmma B fragment directly.
// ============================================================
#define NT_AH 0
#define NT_AL (64 * 40)
#define NT_BH (2 * 64 * 40)
#define NT_BL (3 * 64 * 40)
#define NT_ST_LD 68
#define NT_SMEM_BYTES (4 * 64 * 40 * 2)   // 20480 B (>= 64*68*4=17408 epilogue)

template <int MODE>
__global__ void __launch_bounds__(256) k_nt_wmma(
    const float* __restrict__ A, const float* __restrict__ W,
    const float* __restrict__ addv, float* __restrict__ C) {
    extern __shared__ char smraw[];
    __half* AH = (__half*)smraw + NT_AH;
    __half* AL = (__half*)smraw + NT_AL;
    __half* BH = (__half*)smraw + NT_BH;
    __half* BL = (__half*)smraw + NT_BL;
    float*  ST = (float*)smraw;

    int tid = threadIdx.x, w = tid >> 5;
    int m0 = blockIdx.y * 64, n0 = blockIdx.x * 64;
    int wm = w & 3, wn = w >> 2;     // warp tile: rows wm*16, cols wn*32

    wmma::fragment<wmma::accumulator, 16, 16, 16, float> acc[2];
    wmma::fill_fragment(acc[0], 0.f);
    wmma::fill_fragment(acc[1], 0.f);

    // A: 64x32 f32 tile = 512 float4, 2/thread. B same.
    int ar[2], ac[2];
#pragma unroll
    for (int i = 0; i < 2; i++) {
        int id = tid + 256 * i;
        ar[i] = id >> 3; ac[i] = (id & 7) * 4;
    }

    float4 av[2], bv[2];
#pragma unroll
    for (int i = 0; i < 2; i++) {
        av[i] = *(const float4*)(A + (size_t)(m0 + ar[i]) * ND + ac[i]);
        bv[i] = *(const float4*)(W + (size_t)(n0 + ar[i]) * ND + ac[i]);
    }

    for (int kt = 0; kt < ND / 32; kt++) {
        __syncthreads();
#pragma unroll
        for (int i = 0; i < 2; i++) {
            float xa[4] = {av[i].x, av[i].y, av[i].z, av[i].w};
            float xb[4] = {bv[i].x, bv[i].y, bv[i].z, bv[i].w};
            __half ha[4], la[4], hb[4], lb[4];
#pragma unroll
            for (int j = 0; j < 4; j++) {
                ha[j] = __float2half_rn(xa[j]);
                la[j] = __float2half_rn(xa[j] - __half2float(ha[j]));
                hb[j] = __float2half_rn(xb[j]);
                lb[j] = __float2half_rn(xb[j] - __half2float(hb[j]));
            }
            __half2* pah = (__half2*)&AH[ar[i] * 40 + ac[i]];
            __half2* pal = (__half2*)&AL[ar[i] * 40 + ac[i]];
            __half2* pbh = (__half2*)&BH[ar[i] * 40 + ac[i]];
            __half2* pbl = (__half2*)&BL[ar[i] * 40 + ac[i]];
            pah[0] = __halves2half2(ha[0], ha[1]); pah[1] = __halves2half2(ha[2], ha[3]);
            pal[0] = __halves2half2(la[0], la[1]); pal[1] = __halves2half2(la[2], la[3]);
            pbh[0] = __halves2half2(hb[0], hb[1]); pbh[1] = __halves2half2(hb[2], hb[3]);
            pbl[0] = __halves2half2(lb[0], lb[1]); pbl[1] = __halves2half2(lb[2], lb[3]);
        }
        __syncthreads();
        if (kt + 1 < ND / 32) {
            int k0 = (kt + 1) * 32;
#pragma unroll
            for (int i = 0; i < 2; i++) {
                av[i] = *(const float4*)(A + (size_t)(m0 + ar[i]) * ND + k0 + ac[i]);
                bv[i] = *(const float4*)(W + (size_t)(n0 + ar[i]) * ND + k0 + ac[i]);
            }
        }
#pragma unroll
        for (int ks = 0; ks < 2; ks++) {
            wmma::fragment<wmma::matrix_a, 16, 16, 16, __half, wmma::row_major> fah, fal;
            wmma::load_matrix_sync(fah, &AH[(wm * 16) * 40 + ks * 16], 40);
            wmma::load_matrix_sync(fal, &AL[(wm * 16) * 40 + ks * 16], 40);
#pragma unroll
            for (int nn = 0; nn < 2; nn++) {
                wmma::fragment<wmma::matrix_b, 16, 16, 16, __half, wmma::col_major> fbh, fbl;
                wmma::load_matrix_sync(fbh, &BH[(wn * 32 + nn * 16) * 40 + ks * 16], 40);
                wmma::load_matrix_sync(fbl, &BL[(wn * 32 + nn * 16) * 40 + ks * 16], 40);
                wmma::mma_sync(acc[nn], fah, fbh, acc[nn]);
                wmma::mma_sync(acc[nn], fah, fbl, acc[nn]);
                wmma::mma_sync(acc[nn], fal, fbh, acc[nn]);
            }
        }
    }
    // epilogue via smem staging (reuses tile memory)
    __syncthreads();
#pragma unroll
    for (int nn = 0; nn < 2; nn++)
        wmma::store_matrix_sync(&ST[(wm * 16) * NT_ST_LD + wn * 32 + nn * 16],
                                acc[nn], NT_ST_LD, wmma::mem_row_major);
    __syncthreads();
    int c4 = (tid & 15) * 4;
    float4 adv = *(const float4*)(addv + n0 + c4);
#pragma unroll
    for (int r = 0; r < 4; r++) {
        int row = (tid >> 4) + 16 * r;
        float4 v = *(const float4*)&ST[row * NT_ST_LD + c4];
        v.x += adv.x; v.y += adv.y; v.z += adv.z; v.w += adv.w;
        if (MODE == 0) {
            v.x = tanhf(v.x); v.y = tanhf(v.y); v.z = tanhf(v.z); v.w = tanhf(v.w);
        }
        *(float4*)&C[(size_t)(m0 + row) * ND + n0 + c4] = v;
    }
}

// ============================================================
// K6: big GEMM via wmma fp16 3-term split (f32 acc), M-compacted,
// pure cp.async loop.
// ============================================================
#define BM 128
#define BN 128
#define BK 32
#define NIT (ND / BK)
#define A_LD 40
#define B_LD 136
#define A_SZ (BM * A_LD)
#define B_SZ (BK * B_LD)
#define STG_H (2 * A_SZ + 2 * B_SZ)
#define AHI_O 0
#define ALO_O A_SZ
#define BHI_O (2 * A_SZ)
#define BLO_O (2 * A_SZ + B_SZ)
#define SMEM_BYTES (2 * STG_H * 2)

__device__ __forceinline__ void cpasync16(uint32_t dst, const void* src) {
    asm volatile("cp.async.cg.shared.global [%0], [%1], 16;" :: "r"(dst), "l"(src));
}

__global__ void __launch_bounds__(256, 2) k_mma(
    const __half* __restrict__ Ah, const __half* __restrict__ Al,
    const __half* __restrict__ Bh, const __half* __restrict__ Bl,
    float* __restrict__ C) {
    int m0 = blockIdx.y * BM;
    if (m0 >= g_mcnt[0]) return;
    extern __shared__ __half sm[];
    uint32_t sm_u32 = (uint32_t)__cvta_generic_to_shared(sm);
    int tid = threadIdx.x, wid = tid >> 5;
    int n0 = blockIdx.x * BN;
    int wm = wid & 3, wn = wid >> 2;

    wmma::fragment<wmma::accumulator, 16, 16, 16, float> acc[2][4];
#pragma unroll
    for (int mm = 0; mm < 2; mm++)
#pragma unroll
        for (int nn = 0; nn < 4; nn++) wmma::fill_fragment(acc[mm][nn], 0.f);

    int arow[2], ac8[2];
#pragma unroll
    for (int i = 0; i < 2; i++) {
        int chk = tid + 256 * i;
        arow[i] = chk >> 2;
        ac8[i] = (chk & 3) * 8;
    }
    int brow[2], bc8[2];
#pragma unroll
    for (int i = 0; i < 2; i++) {
        int id = tid + 256 * i;
        brow[i] = id >> 4;
        bc8[i] = (id & 15) * 8;
    }

    const __half* Abh = Ah + (size_t)m0 * ND;
    const __half* Abl = Al + (size_t)m0 * ND;

    auto issue = [&](int kt, int so) {
        int k0 = kt * BK;
#pragma unroll
        for (int i = 0; i < 2; i++) {
            uint32_t dh = sm_u32 + (so + AHI_O + arow[i] * A_LD + ac8[i]) * 2;
            uint32_t dl = sm_u32 + (so + ALO_O + arow[i] * A_LD + ac8[i]) * 2;
            cpasync16(dh, Abh + (size_t)arow[i] * ND + k0 + ac8[i]);
            cpasync16(dl, Abl + (size_t)arow[i] * ND + k0 + ac8[i]);
        }
#pragma unroll
        for (int i = 0; i < 2; i++) {
            uint32_t dh = sm_u32 + (so + BHI_O + brow[i] * B_LD + bc8[i]) * 2;
            uint32_t dl = sm_u32 + (so + BLO_O + brow[i] * B_LD + bc8[i]) * 2;
            cpasync16(dh, Bh + (size_t)(k0 + brow[i]) * ND + n0 + bc8[i]);
            cpasync16(dl, Bl + (size_t)(k0 + brow[i]) * ND + n0 + bc8[i]);
        }
        asm volatile("cp.async.commit_group;");
    };

    issue(0, 0);

    for (int it = 0; it < NIT; it++) {
        int s = it & 1;
        __half* stg = sm + s * STG_H;
        asm volatile("cp.async.wait_group 0;");
        __syncthreads();
        if (it + 1 < NIT) issue(it + 1, (1 - s) * STG_H);
#pragma unroll
        for (int ks = 0; ks < 2; ks++) {
            wmma::fragment<wmma::matrix_a, 16, 16, 16, __half, wmma::row_major> ah[2], al[2];
#pragma unroll
            for (int mm = 0; mm < 2; mm++) {
                const __half* pa = stg + AHI_O + (wm * 32 + mm * 16) * A_LD + ks * 16;
                const __half* pl = stg + ALO_O + (wm * 32 + mm * 16) * A_LD + ks * 16;
                wmma::load_matrix_sync(ah[mm], pa, A_LD);
                wmma::load_matrix_sync(al[mm], pl, A_LD);
            }
#pragma unroll
            for (int nn = 0; nn < 4; nn++) {
                wmma::fragment<wmma::matrix_b, 16, 16, 16, __half, wmma::row_major> bh, bl;
                const __half* pb = stg + BHI_O + (ks * 16) * B_LD + wn * 64 + nn * 16;
                const __half* pl = stg + BLO_O + (ks * 16) * B_LD + wn * 64 + nn * 16;
                wmma::load_matrix_sync(bh, pb, B_LD);
                wmma::load_matrix_sync(bl, pl, B_LD);
#pragma unroll
                for (int mm = 0; mm < 2; mm++) {
                    wmma::mma_sync(acc[mm][nn], ah[mm], bh, acc[mm][nn]);
                    wmma::mma_sync(acc[mm][nn], ah[mm], bl, acc[mm][nn]);
                    wmma::mma_sync(acc[mm][nn], al[mm], bh, acc[mm][nn]);
                }
            }
        }
        // no bottom barrier — next iteration's wait+sync protects stage reuse
    }
#pragma unroll
    for (int mm = 0; mm < 2; mm++)
#pragma unroll
        for (int nn = 0; nn < 4; nn++) {
            float* cp = C + (size_t)(m0 + wm * 32 + mm * 16) * ND + n0 + wn * 64 + nn * 16;
            wmma::store_matrix_sync(cp, acc[mm][nn], ND, wmma::mem_row_major);
        }
}

// ============================================================
// K7: sequential scan — depth-1 prefetch in named registers
// ============================================================
__global__ void __launch_bounds__(256) k_scan(
    const float* __restrict__ sent, const int* __restrict__ lens,
    const float* __restrict__ bias, float* __restrict__ out) {
    int b = blockIdx.x;
    int tid = threadIdx.x;
    __shared__ float s_red[2][16];
    __shared__ float s_absp[NL];
    __shared__ float s_rel[10];
    if (tid < NL) s_absp[tid] = g_absp[tid];
    if (tid < 10) s_rel[tid] = g_relpv[tid];
    int len = lens[b];
    float flen = (float)len;
    float bi = bias[0];
    float4 w4 = *(const float4*)&g_cwu[(size_t)b * ND + tid * 4];
    float4 s4 = make_float4(0.f, 0.f, 0.f, 0.f);
    const float* hb = sent + (size_t)b * NL * ND + tid * 4;
    const float* nb = g_hWn + (size_t)g_off[b] * ND + tid * 4;
    __syncthreads();
    int wid = tid >> 5, lane = tid & 31;
    float4 h = *(const float4*)(hb);
    float4 wn = *(const float4*)(nb);
    for (int l = 0; l < len; l++) {
        float4 h2, wn2;
        if (l + 1 < len) {
            h2 = *(const float4*)(hb + (size_t)(l + 1) * ND);
            wn2 = *(const float4*)(nb + (size_t)(l + 1) * ND);
        }
        float p1 = wn.x * tanhf(s4.x) + wn.y * tanhf(s4.y) +
                   wn.z * tanhf(s4.z) + wn.w * tanhf(s4.w);
        float p2 = h.x * w4.x + h.y * w4.y + h.z * w4.z + h.w * w4.w;
#pragma unroll
        for (int off = 16; off > 0; off >>= 1) {
            p1 += __shfl_xor_sync(0xffffffffu, p1, off);
            p2 += __shfl_xor_sync(0xffffffffu, p2, off);
        }
        int buf = l & 1;
        if (lane == 0) { s_red[buf][wid] = p1; s_red[buf][8 + wid] = p2; }
        __syncthreads();
        float nsum = 0.f, cs = 0.f;
#pragma unroll
        for (int i = 0; i < 8; i++) { nsum += s_red[buf][i]; cs += s_red[buf][8 + i]; }
        int ridx = (int)rintf((float)(l + 1) * 9.0f / flen);
        ridx = ridx < 0 ? 0 : (ridx > 9 ? 9 : ridx);
        float pre = cs + s_absp[l] + s_rel[ridx] + bi;
        float x = pre - nsum;
        float prob = 1.f / (1.f + expf(-x));
        if (tid == 0) out[(size_t)b * NL + l] = prob;
        s4.x += prob * h.x; s4.y += prob * h.y;
        s4.z += prob * h.z; s4.w += prob * h.w;
        h = h2; wn = wn2;
    }
    for (int l = len + tid; l < NL; l += 256) out[(size_t)b * NL + l] = 0.f;
}

// ============================================================
extern "C" void kernel_launch(void* const* d_in, const int* in_sizes, int n_in,
                              void* d_out, int out_size) {
    const float* sent      = (const float*)d_in[0];
    const float* fc_w      = (const float*)d_in[1];
    const float* fc_b      = (const float*)d_in[2];
    const float* content_w = (const float*)d_in[3];
    const float* sal_w     = (const float*)d_in[4];
    const float* nov_w     = (const float*)d_in[5];
    const float* abs_emb   = (const float*)d_in[6];
    const float* rel_emb   = (const float*)d_in[7];
    const float* abs_w     = (const float*)d_in[8];
    const float* rel_w     = (const float*)d_in[9];
    const float* bias      = (const float*)d_in[10];
    const int*   lens      = (const int*)d_in[11];
    float* out = (float*)d_out;

    float *docs, *dv, *cwu, *hWn;
    __half *bhi, *blo, *ahi, *alo;
    cudaGetSymbolAddress((void**)&docs, g_docs);
    cudaGetSymbolAddress((void**)&dv,   g_docvec);
    cudaGetSymbolAddress((void**)&cwu,  g_cwu);
    cudaGetSymbolAddress((void**)&hWn,  g_hWn);
    cudaGetSymbolAddress((void**)&bhi,  g_bhi);
    cudaGetSymbolAddress((void**)&blo,  g_blo);
    cudaGetSymbolAddress((void**)&ahi,  g_ahi);
    cudaGetSymbolAddress((void**)&alo,  g_alo);

    static cudaStream_t sB = nullptr, sC = nullptr;
    static cudaEvent_t evFork = nullptr, evJoin = nullptr, evP = nullptr, evA = nullptr;
    static bool init_done = false;
    if (!init_done) {
        cudaFuncSetAttribute(k_mma, cudaFuncAttributeMaxDynamicSharedMemorySize, SMEM_BYTES);
        cudaStreamCreateWithFlags(&sB, cudaStreamNonBlocking);
        cudaStreamCreateWithFlags(&sC, cudaStreamNonBlocking);
        cudaEventCreateWithFlags(&evFork, cudaEventDisableTiming);
        cudaEventCreateWithFlags(&evJoin, cudaEventDisableTiming);
        cudaEventCreateWithFlags(&evP, cudaEventDisableTiming);
        cudaEventCreateWithFlags(&evA, cudaEventDisableTiming);
        init_done = true;
    }

    // ---- fork: branch B (docs -> doc_vec -> cwu, pos) on sB ----
    cudaEventRecord(evFork, 0);
    cudaStreamWaitEvent(sB, evFork, 0);
    k_docs<<<NB, 256, 0, sB>>>(sent, lens);
    k_pos<<<1, 128, 0, sB>>>(abs_emb, rel_emb, abs_w, rel_w);
    k_nt_wmma<0><<<dim3(ND / 64, NB / 64), 256, NT_SMEM_BYTES, sB>>>(docs, fc_w, fc_b, dv);
    k_nt_wmma<1><<<dim3(ND / 64, NB / 64), 256, NT_SMEM_BYTES, sB>>>(dv, sal_w, content_w, cwu);
    cudaEventRecord(evJoin, sB);

    // ---- branch A: prefix on main; splitA on sC parallel with splitB ----
    k_prefix<<<1, NB>>>(lens);
    cudaEventRecord(evP, 0);
    cudaStreamWaitEvent(sC, evP, 0);
    k_splitA<<<M_PAD, 256, 0, sC>>>(sent, ahi, alo);
    cudaEventRecord(evA, sC);
    k_splitB<<<(ND * ND / 4) / 256, 256>>>(nov_w, bhi, blo);
    cudaStreamWaitEvent(0, evA, 0);
    k_mma<<<dim3(ND / BN, M_TOTAL / BM), 256, SMEM_BYTES>>>(ahi, alo, bhi, blo, hWn);

    // ---- join, then scan ----
    cudaStreamWaitEvent(0, evJoin, 0);
    k_scan<<<NB, 256>>>(sent, lens, bias, out);
}

// round 15
// speedup vs baseline: 1.0396x; 1.0396x over previous
#include <cuda_runtime.h>
#include <cuda_fp16.h>
#include <mma.h>
#include <cstdint>

using namespace nvcuda;

#define NB 512
#define NL 100
#define ND 1024
#define M_TOTAL (NB * NL)   // 51200
#define M_PAD (M_TOTAL + 128)

// ---- scratch (static device arrays; no cudaMalloc allowed) ----
__device__ float  g_docs[NB * ND];
__device__ float  g_docvec[NB * ND];
__device__ float  g_cwu[NB * ND];                 // content_w + sal_w @ doc_vec
__device__ float  g_hWn[(size_t)NB * NL * ND];    // compact hWn
__device__ __half g_bhi[ND * ND];                 // nov_w fp16 hi ([k][n])
__device__ __half g_blo[ND * ND];                 // nov_w fp16 lo
__device__ __half g_ahi[(size_t)M_PAD * ND];      // compact sent fp16 hi
__device__ __half g_alo[(size_t)M_PAD * ND];      // compact sent fp16 lo
__device__ float  g_absp[NL];
__device__ float  g_relpv[10];
__device__ int    g_rowidx[M_PAD];
__device__ int    g_off[NB];
__device__ int    g_mcnt[1];

// ============================================================
// K0: prefix-sum of doc_lens -> offsets + compact row index map
// ============================================================
__global__ void k_prefix(const int* __restrict__ lens) {
    __shared__ int sh[NB];
    int t = threadIdx.x;
    int len = lens[t];
    sh[t] = len;
    __syncthreads();
    for (int off = 1; off < NB; off <<= 1) {
        int add = (t >= off) ? sh[t - off] : 0;
        __syncthreads();
        sh[t] += add;
        __syncthreads();
    }
    int off_b = sh[t] - len;
    g_off[t] = off_b;
    for (int l = 0; l < len; l++) g_rowidx[off_b + l] = t * NL + l;
    if (t == NB - 1) {
        int total = sh[t];
        g_mcnt[0] = total;
        int pad = ((total + 127) / 128) * 128;
        for (int i = total; i < pad; i++) g_rowidx[i] = 0;
    }
}

// ============================================================
// K0b: pre-split compact A rows into fp16 hi/lo (block = one compact row)
// ============================================================
__global__ void __launch_bounds__(256) k_splitA(const float* __restrict__ sent,
                                                __half* __restrict__ ah,
                                                __half* __restrict__ al) {
    int m = blockIdx.x;
    int pad = (g_mcnt[0] + 127) & ~127;
    if (m >= pad) return;
    int src = g_rowidx[m];
    const float4* p = (const float4*)(sent + (size_t)src * ND);
    int t = threadIdx.x;
    float4 v = p[t];
    __half h0 = __float2half_rn(v.x), h1 = __float2half_rn(v.y);
    __half h2 = __float2half_rn(v.z), h3 = __float2half_rn(v.w);
    __half l0 = __float2half_rn(v.x - __half2float(h0));
    __half l1 = __float2half_rn(v.y - __half2float(h1));
    __half l2 = __float2half_rn(v.z - __half2float(h2));
    __half l3 = __float2half_rn(v.w - __half2float(h3));
    __half2* ph = (__half2*)(ah + (size_t)m * ND) + 2 * t;
    __half2* pl = (__half2*)(al + (size_t)m * ND) + 2 * t;
    ph[0] = __halves2half2(h0, h1); ph[1] = __halves2half2(h2, h3);
    pl[0] = __halves2half2(l0, l1); pl[1] = __halves2half2(l2, l3);
}

// ============================================================
// K1: docs[b,d] = sum_{l<len} sent[b,l,d] / len  (float4, block per b)
// ============================================================
__global__ void __launch_bounds__(256) k_docs(const float* __restrict__ sent,
                                              const int* __restrict__ lens) {
    int b = blockIdx.x;
    int t = threadIdx.x;
    int len = lens[b];
    const float4* p = (const float4*)(sent + (size_t)b * NL * ND) + t;
    float4 s = make_float4(0.f, 0.f, 0.f, 0.f);
    for (int l = 0; l < len; l++) {
        float4 v = p[(size_t)l * (ND / 4)];
        s.x += v.x; s.y += v.y; s.z += v.z; s.w += v.w;
    }
    float inv = 1.f / (float)len;
    s.x *= inv; s.y *= inv; s.z *= inv; s.w *= inv;
    ((float4*)g_docs)[b * (ND / 4) + t] = s;
}

// ============================================================
// K2: abs_p / rel_pv dot products
// ============================================================
__global__ void k_pos(const float* __restrict__ abs_emb, const float* __restrict__ rel_emb,
                      const float* __restrict__ abs_w, const float* __restrict__ rel_w) {
    int t = threadIdx.x;
    if (t < NL) {
        float s = 0.f;
        for (int j = 0; j < 50; j++) s += abs_emb[t * 50 + j] * abs_w[j];
        g_absp[t] = s;
    } else if (t >= 100 && t < 110) {
        int i = t - 100;
        float s = 0.f;
        for (int j = 0; j < 50; j++) s += rel_emb[i * 50 + j] * rel_w[j];
        g_relpv[i] = s;
    }
}

// ============================================================
// K3: fp16 split of nov_w ([k][n] row-major)
// ============================================================
__global__ void k_splitB(const float* __restrict__ w, __half* __restrict__ bh,
                         __half* __restrict__ bl) {
    int i = blockIdx.x * blockDim.x + threadIdx.x;
    float4 v = ((const float4*)w)[i];
    __half h0 = __float2half_rn(v.x), h1 = __float2half_rn(v.y);
    __half h2 = __float2half_rn(v.z), h3 = __float2half_rn(v.w);
    __half l0 = __float2half_rn(v.x - __half2float(h0));
    __half l1 = __float2half_rn(v.y - __half2float(h1));
    __half l2 = __float2half_rn(v.z - __half2float(h2));
    __half l3 = __float2half_rn(v.w - __half2float(h3));
    ((__half2*)bh)[2 * i] = __halves2half2(h0, h1);
    ((__half2*)bh)[2 * i + 1] = __halves2half2(h2, h3);
    ((__half2*)bl)[2 * i] = __halves2half2(l0, l1);
    ((__half2*)bl)[2 * i + 1] = __halves2half2(l2, l3);
}

// ============================================================
// K4/K5: NT GEMM via wmma fp16 3-term split, in-kernel splitting.
// CTA tile 64(M) x 128(N), BK=64 (16 k-iters), 8 warps (warp tile 32x32).
// W is [n][k] row-major -> col_major wmma B fragment directly.
// ============================================================
#define NT_LD 72
#define NT_AH 0
#define NT_AL (64 * NT_LD)
#define NT_BH (2 * 64 * NT_LD)
#define NT_BL (2 * 64 * NT_LD + 128 * NT_LD)
#define NT_ST_LD 132
#define NT_SMEM_BYTES ((2 * 64 * NT_LD + 2 * 128 * NT_LD) * 2)   // 55296 B

template <int MODE>
__global__ void __launch_bounds__(256) k_nt_wmma(
    const float* __restrict__ A, const float* __restrict__ W,
    const float* __restrict__ addv, float* __restrict__ C) {
    extern __shared__ char smraw[];
    __half* AH = (__half*)smraw + NT_AH;
    __half* AL = (__half*)smraw + NT_AL;
    __half* BH = (__half*)smraw + NT_BH;
    __half* BL = (__half*)smraw + NT_BL;
    float*  ST = (float*)smraw;

    int tid = threadIdx.x, w = tid >> 5;
    int m0 = blockIdx.y * 64, n0 = blockIdx.x * 128;
    int wm = w & 1, wn = w >> 1;     // warp tile: rows wm*32, cols wn*32

    wmma::fragment<wmma::accumulator, 16, 16, 16, float> acc[2][2];
#pragma unroll
    for (int mm = 0; mm < 2; mm++)
#pragma unroll
        for (int nn = 0; nn < 2; nn++) wmma::fill_fragment(acc[mm][nn], 0.f);

    // A: 64x64 f32 = 1024 float4, 4/thread. B: 128x64 = 2048 float4, 8/thread.
    int ar[4], ac[4], br[8], bc[8];
#pragma unroll
    for (int i = 0; i < 4; i++) {
        int id = tid + 256 * i;
        ar[i] = id >> 4; ac[i] = (id & 15) * 4;
    }
#pragma unroll
    for (int i = 0; i < 8; i++) {
        int id = tid + 256 * i;
        br[i] = id >> 4; bc[i] = (id & 15) * 4;
    }

    float4 av[4], bv[8];
#pragma unroll
    for (int i = 0; i < 4; i++) av[i] = *(const float4*)(A + (size_t)(m0 + ar[i]) * ND + ac[i]);
#pragma unroll
    for (int i = 0; i < 8; i++) bv[i] = *(const float4*)(W + (size_t)(n0 + br[i]) * ND + bc[i]);

    for (int kt = 0; kt < ND / 64; kt++) {
        __syncthreads();
        // split + store current tile
#pragma unroll
        for (int i = 0; i < 4; i++) {
            float x[4] = {av[i].x, av[i].y, av[i].z, av[i].w};
            __half h[4], l[4];
#pragma unroll
            for (int j = 0; j < 4; j++) {
                h[j] = __float2half_rn(x[j]);
                l[j] = __float2half_rn(x[j] - __half2float(h[j]));
            }
            __half2* ph = (__half2*)&AH[ar[i] * NT_LD + ac[i]];
            __half2* pl = (__half2*)&AL[ar[i] * NT_LD + ac[i]];
            ph[0] = __halves2half2(h[0], h[1]); ph[1] = __halves2half2(h[2], h[3]);
            pl[0] = __halves2half2(l[0], l[1]); pl[1] = __halves2half2(l[2], l[3]);
        }
#pragma unroll
        for (int i = 0; i < 8; i++) {
            float x[4] = {bv[i].x, bv[i].y, bv[i].z, bv[i].w};
            __half h[4], l[4];
#pragma unroll
            for (int j = 0; j < 4; j++) {
                h[j] = __float2half_rn(x[j]);
                l[j] = __float2half_rn(x[j] - __half2float(h[j]));
            }
            __half2* ph = (__half2*)&BH[br[i] * NT_LD + bc[i]];
            __half2* pl = (__half2*)&BL[br[i] * NT_LD + bc[i]];
            ph[0] = __halves2half2(h[0], h[1]); ph[1] = __halves2half2(h[2], h[3]);
            pl[0] = __halves2half2(l[0], l[1]); pl[1] = __halves2half2(l[2], l[3]);
        }
        __syncthreads();
        // prefetch next tile while mma runs
        if (kt + 1 < ND / 64) {
            int k0 = (kt + 1) * 64;
#pragma unroll
            for (int i = 0; i < 4; i++)
                av[i] = *(const float4*)(A + (size_t)(m0 + ar[i]) * ND + k0 + ac[i]);
#pragma unroll
            for (int i = 0; i < 8; i++)
                bv[i] = *(const float4*)(W + (size_t)(n0 + br[i]) * ND + k0 + bc[i]);
        }
#pragma unroll
        for (int ks = 0; ks < 4; ks++) {
            wmma::fragment<wmma::matrix_a, 16, 16, 16, __half, wmma::row_major> fah[2], fal[2];
#pragma unroll
            for (int mm = 0; mm < 2; mm++) {
                wmma::load_matrix_sync(fah[mm], &AH[(wm * 32 + mm * 16) * NT_LD + ks * 16], NT_LD);
                wmma::load_matrix_sync(fal[mm], &AL[(wm * 32 + mm * 16) * NT_LD + ks * 16], NT_LD);
            }
#pragma unroll
            for (int nn = 0; nn < 2; nn++) {
                wmma::fragment<wmma::matrix_b, 16, 16, 16, __half, wmma::col_major> fbh, fbl;
                wmma::load_matrix_sync(fbh, &BH[(wn * 32 + nn * 16) * NT_LD + ks * 16], NT_LD);
                wmma::load_matrix_sync(fbl, &BL[(wn * 32 + nn * 16) * NT_LD + ks * 16], NT_LD);
#pragma unroll
                for (int mm = 0; mm < 2; mm++) {
                    wmma::mma_sync(acc[mm][nn], fah[mm], fbh, acc[mm][nn]);
                    wmma::mma_sync(acc[mm][nn], fah[mm], fbl, acc[mm][nn]);
                    wmma::mma_sync(acc[mm][nn], fal[mm], fbh, acc[mm][nn]);
                }
            }
        }
    }
    // epilogue via smem staging (reuses tile memory)
    __syncthreads();
#pragma unroll
    for (int mm = 0; mm < 2; mm++)
#pragma unroll
        for (int nn = 0; nn < 2; nn++)
            wmma::store_matrix_sync(&ST[(wm * 32 + mm * 16) * NT_ST_LD + wn * 32 + nn * 16],
                                    acc[mm][nn], NT_ST_LD, wmma::mem_row_major);
    __syncthreads();
    int c4 = (tid & 31) * 4;
    float4 adv = *(const float4*)(addv + n0 + c4);
#pragma unroll
    for (int r = 0; r < 8; r++) {
        int row = (tid >> 5) + 8 * r;
        float4 v = *(const float4*)&ST[row * NT_ST_LD + c4];
        v.x += adv.x; v.y += adv.y; v.z += adv.z; v.w += adv.w;
        if (MODE == 0) {
            v.x = tanhf(v.x); v.y = tanhf(v.y); v.z = tanhf(v.z); v.w = tanhf(v.w);
        }
        *(float4*)&C[(size_t)(m0 + row) * ND + n0 + c4] = v;
    }
}

// ============================================================
// K6: big GEMM via wmma fp16 3-term split (f32 acc), M-compacted,
// pure cp.async loop.
// ============================================================
#define BM 128
#define BN 128
#define BK 32
#define NIT (ND / BK)
#define A_LD 40
#define B_LD 136
#define A_SZ (BM * A_LD)
#define B_SZ (BK * B_LD)
#define STG_H (2 * A_SZ + 2 * B_SZ)
#define AHI_O 0
#define ALO_O A_SZ
#define BHI_O (2 * A_SZ)
#define BLO_O (2 * A_SZ + B_SZ)
#define SMEM_BYTES (2 * STG_H * 2)

__device__ __forceinline__ void cpasync16(uint32_t dst, const void* src) {
    asm volatile("cp.async.cg.shared.global [%0], [%1], 16;" :: "r"(dst), "l"(src));
}

__global__ void __launch_bounds__(256, 2) k_mma(
    const __half* __restrict__ Ah, const __half* __restrict__ Al,
    const __half* __restrict__ Bh, const __half* __restrict__ Bl,
    float* __restrict__ C) {
    int m0 = blockIdx.y * BM;
    if (m0 >= g_mcnt[0]) return;
    extern __shared__ __half sm[];
    uint32_t sm_u32 = (uint32_t)__cvta_generic_to_shared(sm);
    int tid = threadIdx.x, wid = tid >> 5;
    int n0 = blockIdx.x * BN;
    int wm = wid & 3, wn = wid >> 2;

    wmma::fragment<wmma::accumulator, 16, 16, 16, float> acc[2][4];
#pragma unroll
    for (int mm = 0; mm < 2; mm++)
#pragma unroll
        for (int nn = 0; nn < 4; nn++) wmma::fill_fragment(acc[mm][nn], 0.f);

    int arow[2], ac8[2];
#pragma unroll
    for (int i = 0; i < 2; i++) {
        int chk = tid + 256 * i;
        arow[i] = chk >> 2;
        ac8[i] = (chk & 3) * 8;
    }
    int brow[2], bc8[2];
#pragma unroll
    for (int i = 0; i < 2; i++) {
        int id = tid + 256 * i;
        brow[i] = id >> 4;
        bc8[i] = (id & 15) * 8;
    }

    const __half* Abh = Ah + (size_t)m0 * ND;
    const __half* Abl = Al + (size_t)m0 * ND;

    auto issue = [&](int kt, int so) {
        int k0 = kt * BK;
#pragma unroll
        for (int i = 0; i < 2; i++) {
            uint32_t dh = sm_u32 + (so + AHI_O + arow[i] * A_LD + ac8[i]) * 2;
            uint32_t dl = sm_u32 + (so + ALO_O + arow[i] * A_LD + ac8[i]) * 2;
            cpasync16(dh, Abh + (size_t)arow[i] * ND + k0 + ac8[i]);
            cpasync16(dl, Abl + (size_t)arow[i] * ND + k0 + ac8[i]);
        }
#pragma unroll
        for (int i = 0; i < 2; i++) {
            uint32_t dh = sm_u32 + (so + BHI_O + brow[i] * B_LD + bc8[i]) * 2;
            uint32_t dl = sm_u32 + (so + BLO_O + brow[i] * B_LD + bc8[i]) * 2;
            cpasync16(dh, Bh + (size_t)(k0 + brow[i]) * ND + n0 + bc8[i]);
            cpasync16(dl, Bl + (size_t)(k0 + brow[i]) * ND + n0 + bc8[i]);
        }
        asm volatile("cp.async.commit_group;");
    };

    issue(0, 0);

    for (int it = 0; it < NIT; it++) {
        int s = it & 1;
        __half* stg = sm + s * STG_H;
        asm volatile("cp.async.wait_group 0;");
        __syncthreads();
        if (it + 1 < NIT) issue(it + 1, (1 - s) * STG_H);
#pragma unroll
        for (int ks = 0; ks < 2; ks++) {
            wmma::fragment<wmma::matrix_a, 16, 16, 16, __half, wmma::row_major> ah[2], al[2];
#pragma unroll
            for (int mm = 0; mm < 2; mm++) {
                const __half* pa = stg + AHI_O + (wm * 32 + mm * 16) * A_LD + ks * 16;
                const __half* pl = stg + ALO_O + (wm * 32 + mm * 16) * A_LD + ks * 16;
                wmma::load_matrix_sync(ah[mm], pa, A_LD);
                wmma::load_matrix_sync(al[mm], pl, A_LD);
            }
#pragma unroll
            for (int nn = 0; nn < 4; nn++) {
                wmma::fragment<wmma::matrix_b, 16, 16, 16, __half, wmma::row_major> bh, bl;
                const __half* pb = stg + BHI_O + (ks * 16) * B_LD + wn * 64 + nn * 16;
                const __half* pl = stg + BLO_O + (ks * 16) * B_LD + wn * 64 + nn * 16;
                wmma::load_matrix_sync(bh, pb, B_LD);
                wmma::load_matrix_sync(bl, pl, B_LD);
#pragma unroll
                for (int mm = 0; mm < 2; mm++) {
                    wmma::mma_sync(acc[mm][nn], ah[mm], bh, acc[mm][nn]);
                    wmma::mma_sync(acc[mm][nn], ah[mm], bl, acc[mm][nn]);
                    wmma::mma_sync(acc[mm][nn], al[mm], bh, acc[mm][nn]);
                }
            }
        }
        // no bottom barrier — next iteration's wait+sync protects stage reuse
    }
#pragma unroll
    for (int mm = 0; mm < 2; mm++)
#pragma unroll
        for (int nn = 0; nn < 4; nn++) {
            float* cp = C + (size_t)(m0 + wm * 32 + mm * 16) * ND + n0 + wn * 64 + nn * 16;
            wmma::store_matrix_sync(cp, acc[mm][nn], ND, wmma::mem_row_major);
        }
}

// ============================================================
// K7: sequential scan — depth-1 prefetch in named registers
// ============================================================
__global__ void __launch_bounds__(256) k_scan(
    const float* __restrict__ sent, const int* __restrict__ lens,
    const float* __restrict__ bias, float* __restrict__ out) {
    int b = blockIdx.x;
    int tid = threadIdx.x;
    __shared__ float s_red[2][16];
    __shared__ float s_absp[NL];
    __shared__ float s_rel[10];
    if (tid < NL) s_absp[tid] = g_absp[tid];
    if (tid < 10) s_rel[tid] = g_relpv[tid];
    int len = lens[b];
    float flen = (float)len;
    float bi = bias[0];
    float4 w4 = *(const float4*)&g_cwu[(size_t)b * ND + tid * 4];
    float4 s4 = make_float4(0.f, 0.f, 0.f, 0.f);
    const float* hb = sent + (size_t)b * NL * ND + tid * 4;
    const float* nb = g_hWn + (size_t)g_off[b] * ND + tid * 4;
    __syncthreads();
    int wid = tid >> 5, lane = tid & 31;
    float4 h = *(const float4*)(hb);
    float4 wn = *(const float4*)(nb);
    for (int l = 0; l < len; l++) {
        float4 h2, wn2;
        if (l + 1 < len) {
            h2 = *(const float4*)(hb + (size_t)(l + 1) * ND);
            wn2 = *(const float4*)(nb + (size_t)(l + 1) * ND);
        }
        float p1 = wn.x * tanhf(s4.x) + wn.y * tanhf(s4.y) +
                   wn.z * tanhf(s4.z) + wn.w * tanhf(s4.w);
        float p2 = h.x * w4.x + h.y * w4.y + h.z * w4.z + h.w * w4.w;
#pragma unroll
        for (int off = 16; off > 0; off >>= 1) {
            p1 += __shfl_xor_sync(0xffffffffu, p1, off);
            p2 += __shfl_xor_sync(0xffffffffu, p2, off);
        }
        int buf = l & 1;
        if (lane == 0) { s_red[buf][wid] = p1; s_red[buf][8 + wid] = p2; }
        __syncthreads();
        float nsum = 0.f, cs = 0.f;
#pragma unroll
        for (int i = 0; i < 8; i++) { nsum += s_red[buf][i]; cs += s_red[buf][8 + i]; }
        int ridx = (int)rintf((float)(l + 1) * 9.0f / flen);
        ridx = ridx < 0 ? 0 : (ridx > 9 ? 9 : ridx);
        float pre = cs + s_absp[l] + s_rel[ridx] + bi;
        float x = pre - nsum;
        float prob = 1.f / (1.f + expf(-x));
        if (tid == 0) out[(size_t)b * NL + l] = prob;
        s4.x += prob * h.x; s4.y += prob * h.y;
        s4.z += prob * h.z; s4.w += prob * h.w;
        h = h2; wn = wn2;
    }
    for (int l = len + tid; l < NL; l += 256) out[(size_t)b * NL + l] = 0.f;
}

// ============================================================
extern "C" void kernel_launch(void* const* d_in, const int* in_sizes, int n_in,
                              void* d_out, int out_size) {
    const float* sent      = (const float*)d_in[0];
    const float* fc_w      = (const float*)d_in[1];
    const float* fc_b      = (const float*)d_in[2];
    const float* content_w = (const float*)d_in[3];
    const float* sal_w     = (const float*)d_in[4];
    const float* nov_w     = (const float*)d_in[5];
    const float* abs_emb   = (const float*)d_in[6];
    const float* rel_emb   = (const float*)d_in[7];
    const float* abs_w     = (const float*)d_in[8];
    const float* rel_w     = (const float*)d_in[9];
    const float* bias      = (const float*)d_in[10];
    const int*   lens      = (const int*)d_in[11];
    float* out = (float*)d_out;

    float *docs, *dv, *cwu, *hWn;
    __half *bhi, *blo, *ahi, *alo;
    cudaGetSymbolAddress((void**)&docs, g_docs);
    cudaGetSymbolAddress((void**)&dv,   g_docvec);
    cudaGetSymbolAddress((void**)&cwu,  g_cwu);
    cudaGetSymbolAddress((void**)&hWn,  g_hWn);
    cudaGetSymbolAddress((void**)&bhi,  g_bhi);
    cudaGetSymbolAddress((void**)&blo,  g_blo);
    cudaGetSymbolAddress((void**)&ahi,  g_ahi);
    cudaGetSymbolAddress((void**)&alo,  g_alo);

    static cudaStream_t sB = nullptr, sC = nullptr;
    static cudaEvent_t evFork = nullptr, evJoin = nullptr, evP = nullptr, evA = nullptr;
    static bool init_done = false;
    if (!init_done) {
        cudaFuncSetAttribute(k_mma, cudaFuncAttributeMaxDynamicSharedMemorySize, SMEM_BYTES);
        cudaFuncSetAttribute(k_nt_wmma<0>, cudaFuncAttributeMaxDynamicSharedMemorySize, NT_SMEM_BYTES);
        cudaFuncSetAttribute(k_nt_wmma<1>, cudaFuncAttributeMaxDynamicSharedMemorySize, NT_SMEM_BYTES);
        cudaStreamCreateWithFlags(&sB, cudaStreamNonBlocking);
        cudaStreamCreateWithFlags(&sC, cudaStreamNonBlocking);
        cudaEventCreateWithFlags(&evFork, cudaEventDisableTiming);
        cudaEventCreateWithFlags(&evJoin, cudaEventDisableTiming);
        cudaEventCreateWithFlags(&evP, cudaEventDisableTiming);
        cudaEventCreateWithFlags(&evA, cudaEventDisableTiming);
        init_done = true;
    }

    // ---- fork: branch B (docs -> doc_vec -> cwu, pos) on sB ----
    cudaEventRecord(evFork, 0);
    cudaStreamWaitEvent(sB, evFork, 0);
    k_docs<<<NB, 256, 0, sB>>>(sent, lens);
    k_pos<<<1, 128, 0, sB>>>(abs_emb, rel_emb, abs_w, rel_w);
    k_nt_wmma<0><<<dim3(ND / 128, NB / 64), 256, NT_SMEM_BYTES, sB>>>(docs, fc_w, fc_b, dv);
    k_nt_wmma<1><<<dim3(ND / 128, NB / 64), 256, NT_SMEM_BYTES, sB>>>(dv, sal_w, content_w, cwu);
    cudaEventRecord(evJoin, sB);

    // ---- branch A: prefix on main; splitA on sC parallel with splitB ----
    k_prefix<<<1, NB>>>(lens);
    cudaEventRecord(evP, 0);
    cudaStreamWaitEvent(sC, evP, 0);
    k_splitA<<<M_PAD, 256, 0, sC>>>(sent, ahi, alo);
    cudaEventRecord(evA, sC);
    k_splitB<<<(ND * ND / 4) / 256, 256>>>(nov_w, bhi, blo);
    cudaStreamWaitEvent(0, evA, 0);
    k_mma<<<dim3(ND / BN, M_TOTAL / BM), 256, SMEM_BYTES>>>(ahi, alo, bhi, blo, hWn);

    // ---- join, then scan ----
    cudaStreamWaitEvent(0, evJoin, 0);
    k_scan<<<NB, 256>>>(sent, lens, bias, out);
}

// round 16
// speedup vs baseline: 1.1065x; 1.0643x over previous
#include <cuda_runtime.h>
#include <cuda_fp16.h>
#include <mma.h>
#include <cstdint>

using namespace nvcuda;

#define NB 512
#define NL 100
#define ND 1024
#define M_TOTAL (NB * NL)   // 51200
#define M_PAD (M_TOTAL + 128)

// ---- scratch (static device arrays; no cudaMalloc allowed) ----
__device__ float  g_docs[NB * ND];
__device__ float  g_docvec[NB * ND];
__device__ float  g_cwu[NB * ND];                 // content_w + sal_w @ doc_vec
__device__ float  g_hWn[(size_t)NB * NL * ND];    // compact hWn
__device__ __half g_bhi[ND * ND];                 // nov_w fp16 hi ([k][n])
__device__ __half g_blo[ND * ND];                 // nov_w fp16 lo
__device__ float  g_absp[NL];
__device__ float  g_relpv[10];
__device__ int    g_rowidx[M_PAD];
__device__ int    g_off[NB];
__device__ int    g_mcnt[1];

// ============================================================
// K0: prefix-sum of doc_lens -> offsets + compact row index map
// ============================================================
__global__ void k_prefix(const int* __restrict__ lens) {
    __shared__ int sh[NB];
    int t = threadIdx.x;
    int len = lens[t];
    sh[t] = len;
    __syncthreads();
    for (int off = 1; off < NB; off <<= 1) {
        int add = (t >= off) ? sh[t - off] : 0;
        __syncthreads();
        sh[t] += add;
        __syncthreads();
    }
    int off_b = sh[t] - len;
    g_off[t] = off_b;
    for (int l = 0; l < len; l++) g_rowidx[off_b + l] = t * NL + l;
    if (t == NB - 1) {
        int total = sh[t];
        g_mcnt[0] = total;
        int pad = ((total + 127) / 128) * 128;
        for (int i = total; i < pad; i++) g_rowidx[i] = 0;
    }
}

// ============================================================
// K1: docs[b,d] = sum_{l<len} sent[b,l,d] / len  (R13 form)
// ============================================================
__global__ void k_docs(const float* __restrict__ sent, const int* __restrict__ lens) {
    int d = blockIdx.x * blockDim.x + threadIdx.x;
    int b = blockIdx.y;
    int len = lens[b];
    const float* p = sent + ((size_t)b * NL) * ND + d;
    float s = 0.f;
    for (int l = 0; l < len; l++) s += p[(size_t)l * ND];
    g_docs[b * ND + d] = s / (float)len;
}

// ============================================================
// K2: abs_p / rel_pv dot products
// ============================================================
__global__ void k_pos(const float* __restrict__ abs_emb, const float* __restrict__ rel_emb,
                      const float* __restrict__ abs_w, const float* __restrict__ rel_w) {
    int t = threadIdx.x;
    if (t < NL) {
        float s = 0.f;
        for (int j = 0; j < 50; j++) s += abs_emb[t * 50 + j] * abs_w[j];
        g_absp[t] = s;
    } else if (t >= 100 && t < 110) {
        int i = t - 100;
        float s = 0.f;
        for (int j = 0; j < 50; j++) s += rel_emb[i * 50 + j] * rel_w[j];
        g_relpv[i] = s;
    }
}

// ============================================================
// K3: fp16 split of nov_w ([k][n] row-major)
// ============================================================
__global__ void k_splitB(const float* __restrict__ w, __half* __restrict__ bh,
                         __half* __restrict__ bl) {
    int i = blockIdx.x * blockDim.x + threadIdx.x;
    float4 v = ((const float4*)w)[i];
    __half h0 = __float2half_rn(v.x), h1 = __float2half_rn(v.y);
    __half h2 = __float2half_rn(v.z), h3 = __float2half_rn(v.w);
    __half l0 = __float2half_rn(v.x - __half2float(h0));
    __half l1 = __float2half_rn(v.y - __half2float(h1));
    __half l2 = __float2half_rn(v.z - __half2float(h2));
    __half l3 = __float2half_rn(v.w - __half2float(h3));
    ((__half2*)bh)[2 * i] = __halves2half2(h0, h1);
    ((__half2*)bh)[2 * i + 1] = __halves2half2(h2, h3);
    ((__half2*)bl)[2 * i] = __halves2half2(l0, l1);
    ((__half2*)bl)[2 * i + 1] = __halves2half2(l2, l3);
}

// ============================================================
// K4/K5: NT GEMM via wmma fp16 3-term split, in-kernel splitting.
// CTA tile 64(M) x 128(N), BK=64 (16 k-iters), 8 warps (warp tile 32x32).
// ============================================================
#define NT_LD 72
#define NT_AH 0
#define NT_AL (64 * NT_LD)
#define NT_BH (2 * 64 * NT_LD)
#define NT_BL (2 * 64 * NT_LD + 128 * NT_LD)
#define NT_ST_LD 132
#define NT_SMEM_BYTES ((2 * 64 * NT_LD + 2 * 128 * NT_LD) * 2)   // 55296 B

template <int MODE>
__global__ void __launch_bounds__(256) k_nt_wmma(
    const float* __restrict__ A, const float* __restrict__ W,
    const float* __restrict__ addv, float* __restrict__ C) {
    extern __shared__ char smraw[];
    __half* AH = (__half*)smraw + NT_AH;
    __half* AL = (__half*)smraw + NT_AL;
    __half* BH = (__half*)smraw + NT_BH;
    __half* BL = (__half*)smraw + NT_BL;
    float*  ST = (float*)smraw;

    int tid = threadIdx.x, w = tid >> 5;
    int m0 = blockIdx.y * 64, n0 = blockIdx.x * 128;
    int wm = w & 1, wn = w >> 1;

    wmma::fragment<wmma::accumulator, 16, 16, 16, float> acc[2][2];
#pragma unroll
    for (int mm = 0; mm < 2; mm++)
#pragma unroll
        for (int nn = 0; nn < 2; nn++) wmma::fill_fragment(acc[mm][nn], 0.f);

    int ar[4], ac[4], br[8], bc[8];
#pragma unroll
    for (int i = 0; i < 4; i++) {
        int id = tid + 256 * i;
        ar[i] = id >> 4; ac[i] = (id & 15) * 4;
    }
#pragma unroll
    for (int i = 0; i < 8; i++) {
        int id = tid + 256 * i;
        br[i] = id >> 4; bc[i] = (id & 15) * 4;
    }

    float4 av[4], bv[8];
#pragma unroll
    for (int i = 0; i < 4; i++) av[i] = *(const float4*)(A + (size_t)(m0 + ar[i]) * ND + ac[i]);
#pragma unroll
    for (int i = 0; i < 8; i++) bv[i] = *(const float4*)(W + (size_t)(n0 + br[i]) * ND + bc[i]);

    for (int kt = 0; kt < ND / 64; kt++) {
        __syncthreads();
#pragma unroll
        for (int i = 0; i < 4; i++) {
            float x[4] = {av[i].x, av[i].y, av[i].z, av[i].w};
            __half h[4], l[4];
#pragma unroll
            for (int j = 0; j < 4; j++) {
                h[j] = __float2half_rn(x[j]);
                l[j] = __float2half_rn(x[j] - __half2float(h[j]));
            }
            __half2* ph = (__half2*)&AH[ar[i] * NT_LD + ac[i]];
            __half2* pl = (__half2*)&AL[ar[i] * NT_LD + ac[i]];
            ph[0] = __halves2half2(h[0], h[1]); ph[1] = __halves2half2(h[2], h[3]);
            pl[0] = __halves2half2(l[0], l[1]); pl[1] = __halves2half2(l[2], l[3]);
        }
#pragma unroll
        for (int i = 0; i < 8; i++) {
            float x[4] = {bv[i].x, bv[i].y, bv[i].z, bv[i].w};
            __half h[4], l[4];
#pragma unroll
            for (int j = 0; j < 4; j++) {
                h[j] = __float2half_rn(x[j]);
                l[j] = __float2half_rn(x[j] - __half2float(h[j]));
            }
            __half2* ph = (__half2*)&BH[br[i] * NT_LD + bc[i]];
            __half2* pl = (__half2*)&BL[br[i] * NT_LD + bc[i]];
            ph[0] = __halves2half2(h[0], h[1]); ph[1] = __halves2half2(h[2], h[3]);
            pl[0] = __halves2half2(l[0], l[1]); pl[1] = __halves2half2(l[2], l[3]);
        }
        __syncthreads();
        if (kt + 1 < ND / 64) {
            int k0 = (kt + 1) * 64;
#pragma unroll
            for (int i = 0; i < 4; i++)
                av[i] = *(const float4*)(A + (size_t)(m0 + ar[i]) * ND + k0 + ac[i]);
#pragma unroll
            for (int i = 0; i < 8; i++)
                bv[i] = *(const float4*)(W + (size_t)(n0 + br[i]) * ND + k0 + bc[i]);
        }
#pragma unroll
        for (int ks = 0; ks < 4; ks++) {
            wmma::fragment<wmma::matrix_a, 16, 16, 16, __half, wmma::row_major> fah[2], fal[2];
#pragma unroll
            for (int mm = 0; mm < 2; mm++) {
                wmma::load_matrix_sync(fah[mm], &AH[(wm * 32 + mm * 16) * NT_LD + ks * 16], NT_LD);
                wmma::load_matrix_sync(fal[mm], &AL[(wm * 32 + mm * 16) * NT_LD + ks * 16], NT_LD);
            }
#pragma unroll
            for (int nn = 0; nn < 2; nn++) {
                wmma::fragment<wmma::matrix_b, 16, 16, 16, __half, wmma::col_major> fbh, fbl;
                wmma::load_matrix_sync(fbh, &BH[(wn * 32 + nn * 16) * NT_LD + ks * 16], NT_LD);
                wmma::load_matrix_sync(fbl, &BL[(wn * 32 + nn * 16) * NT_LD + ks * 16], NT_LD);
#pragma unroll
                for (int mm = 0; mm < 2; mm++) {
                    wmma::mma_sync(acc[mm][nn], fah[mm], fbh, acc[mm][nn]);
                    wmma::mma_sync(acc[mm][nn], fah[mm], fbl, acc[mm][nn]);
                    wmma::mma_sync(acc[mm][nn], fal[mm], fbh, acc[mm][nn]);
                }
            }
        }
    }
    __syncthreads();
#pragma unroll
    for (int mm = 0; mm < 2; mm++)
#pragma unroll
        for (int nn = 0; nn < 2; nn++)
            wmma::store_matrix_sync(&ST[(wm * 32 + mm * 16) * NT_ST_LD + wn * 32 + nn * 16],
                                    acc[mm][nn], NT_ST_LD, wmma::mem_row_major);
    __syncthreads();
    int c4 = (tid & 31) * 4;
    float4 adv = *(const float4*)(addv + n0 + c4);
#pragma unroll
    for (int r = 0; r < 8; r++) {
        int row = (tid >> 5) + 8 * r;
        float4 v = *(const float4*)&ST[row * NT_ST_LD + c4];
        v.x += adv.x; v.y += adv.y; v.z += adv.z; v.w += adv.w;
        if (MODE == 0) {
            v.x = tanhf(v.x); v.y = tanhf(v.y); v.z = tanhf(v.z); v.w = tanhf(v.w);
        }
        *(float4*)&C[(size_t)(m0 + row) * ND + n0 + c4] = v;
    }
}

// ============================================================
// K6: big GEMM via wmma fp16 3-term split (f32 acc), M-compacted.
// A: in-kernel fp32->hi/lo split (LDG at top, STS at bottom — one sync/iter).
// B: pre-split, pure cp.async.
// ============================================================
#define BM 128
#define BN 128
#define BK 32
#define NIT (ND / BK)
#define A_LD 40
#define B_LD 136
#define A_SZ (BM * A_LD)
#define B_SZ (BK * B_LD)
#define STG_H (2 * A_SZ + 2 * B_SZ)
#define AHI_O 0
#define ALO_O A_SZ
#define BHI_O (2 * A_SZ)
#define BLO_O (2 * A_SZ + B_SZ)
#define SMEM_BYTES (2 * STG_H * 2)

__device__ __forceinline__ void cpasync16(uint32_t dst, const void* src) {
    asm volatile("cp.async.cg.shared.global [%0], [%1], 16;" :: "r"(dst), "l"(src));
}

__global__ void __launch_bounds__(256, 2) k_mma(
    const float* __restrict__ A, const __half* __restrict__ Bh,
    const __half* __restrict__ Bl, float* __restrict__ C) {
    int m0 = blockIdx.y * BM;
    if (m0 >= g_mcnt[0]) return;
    extern __shared__ __half sm[];
    uint32_t sm_u32 = (uint32_t)__cvta_generic_to_shared(sm);
    int tid = threadIdx.x, wid = tid >> 5;
    int n0 = blockIdx.x * BN;
    int wm = wid & 3, wn = wid >> 2;

    wmma::fragment<wmma::accumulator, 16, 16, 16, float> acc[2][4];
#pragma unroll
    for (int mm = 0; mm < 2; mm++)
#pragma unroll
        for (int nn = 0; nn < 4; nn++) wmma::fill_fragment(acc[mm][nn], 0.f);

    // A loader: 128 rows x 32 f32 cols = 1024 float4, 4/thread, via rowidx
    int arow[4], ac4[4];
    const float* Abase[4];
#pragma unroll
    for (int i = 0; i < 4; i++) {
        int id = tid + 256 * i;
        arow[i] = id >> 3;
        ac4[i] = (id & 7) * 4;
        Abase[i] = A + (size_t)g_rowidx[m0 + arow[i]] * ND + ac4[i];
    }
    // B cp.async mapping
    int brow[2], bc8[2];
#pragma unroll
    for (int i = 0; i < 2; i++) {
        int id = tid + 256 * i;
        brow[i] = id >> 4;
        bc8[i] = (id & 15) * 8;
    }

    auto issueB = [&](int kt, int so) {
        int k0 = kt * BK;
#pragma unroll
        for (int i = 0; i < 2; i++) {
            uint32_t dh = sm_u32 + (so + BHI_O + brow[i] * B_LD + bc8[i]) * 2;
            uint32_t dl = sm_u32 + (so + BLO_O + brow[i] * B_LD + bc8[i]) * 2;
            cpasync16(dh, Bh + (size_t)(k0 + brow[i]) * ND + n0 + bc8[i]);
            cpasync16(dl, Bl + (size_t)(k0 + brow[i]) * ND + n0 + bc8[i]);
        }
        asm volatile("cp.async.commit_group;");
    };
    auto stsA = [&](int so, const float4* av) {
#pragma unroll
        for (int i = 0; i < 4; i++) {
            float x[4] = {av[i].x, av[i].y, av[i].z, av[i].w};
            __half h[4], l[4];
#pragma unroll
            for (int j = 0; j < 4; j++) {
                h[j] = __float2half_rn(x[j]);
                l[j] = __float2half_rn(x[j] - __half2float(h[j]));
            }
            __half2* ph = (__half2*)&sm[so + AHI_O + arow[i] * A_LD + ac4[i]];
            __half2* pl = (__half2*)&sm[so + ALO_O + arow[i] * A_LD + ac4[i]];
            ph[0] = __halves2half2(h[0], h[1]); ph[1] = __halves2half2(h[2], h[3]);
            pl[0] = __halves2half2(l[0], l[1]); pl[1] = __halves2half2(l[2], l[3]);
        }
    };

    float4 av[4];
    // prologue: tile 0
#pragma unroll
    for (int i = 0; i < 4; i++) av[i] = *(const float4*)(Abase[i]);
    issueB(0, 0);
    stsA(0, av);

    for (int it = 0; it < NIT; it++) {
        int s = it & 1;
        __half* stg = sm + s * STG_H;
        asm volatile("cp.async.wait_group 0;");
        __syncthreads();                    // stage s ready (B via cp.async, A via STS before this sync)
        if (it + 1 < NIT) {
            issueB(it + 1, (1 - s) * STG_H);
            int k0 = (it + 1) * BK;
#pragma unroll
            for (int i = 0; i < 4; i++) av[i] = *(const float4*)(Abase[i] + k0);  // LDG in flight over compute
        }
#pragma unroll
        for (int ks = 0; ks < 2; ks++) {
            wmma::fragment<wmma::matrix_a, 16, 16, 16, __half, wmma::row_major> ah[2], al[2];
#pragma unroll
            for (int mm = 0; mm < 2; mm++) {
                const __half* pa = stg + AHI_O + (wm * 32 + mm * 16) * A_LD + ks * 16;
                const __half* pl = stg + ALO_O + (wm * 32 + mm * 16) * A_LD + ks * 16;
                wmma::load_matrix_sync(ah[mm], pa, A_LD);
                wmma::load_matrix_sync(al[mm], pl, A_LD);
            }
#pragma unroll
            for (int nn = 0; nn < 4; nn++) {
                wmma::fragment<wmma::matrix_b, 16, 16, 16, __half, wmma::row_major> bh, bl;
                const __half* pb = stg + BHI_O + (ks * 16) * B_LD + wn * 64 + nn * 16;
                const __half* pl = stg + BLO_O + (ks * 16) * B_LD + wn * 64 + nn * 16;
                wmma::load_matrix_sync(bh, pb, B_LD);
                wmma::load_matrix_sync(bl, pl, B_LD);
#pragma unroll
                for (int mm = 0; mm < 2; mm++) {
                    wmma::mma_sync(acc[mm][nn], ah[mm], bh, acc[mm][nn]);
                    wmma::mma_sync(acc[mm][nn], ah[mm], bl, acc[mm][nn]);
                    wmma::mma_sync(acc[mm][nn], al[mm], bh, acc[mm][nn]);
                }
            }
        }
        // STS A(it+1) into stage 1-s; safe: all warps passed this iter's top sync,
        // and STS completes before the next top sync drains it.
        if (it + 1 < NIT) stsA((1 - s) * STG_H, av);
    }
#pragma unroll
    for (int mm = 0; mm < 2; mm++)
#pragma unroll
        for (int nn = 0; nn < 4; nn++) {
            float* cp = C + (size_t)(m0 + wm * 32 + mm * 16) * ND + n0 + wn * 64 + nn * 16;
            wmma::store_matrix_sync(cp, acc[mm][nn], ND, wmma::mem_row_major);
        }
}

// ============================================================
// K7: sequential scan — depth-1 prefetch in named registers
// ============================================================
__global__ void __launch_bounds__(256) k_scan(
    const float* __restrict__ sent, const int* __restrict__ lens,
    const float* __restrict__ bias, float* __restrict__ out) {
    int b = blockIdx.x;
    int tid = threadIdx.x;
    __shared__ float s_red[2][16];
    __shared__ float s_absp[NL];
    __shared__ float s_rel[10];
    if (tid < NL) s_absp[tid] = g_absp[tid];
    if (tid < 10) s_rel[tid] = g_relpv[tid];
    int len = lens[b];
    float flen = (float)len;
    float bi = bias[0];
    float4 w4 = *(const float4*)&g_cwu[(size_t)b * ND + tid * 4];
    float4 s4 = make_float4(0.f, 0.f, 0.f, 0.f);
    const float* hb = sent + (size_t)b * NL * ND + tid * 4;
    const float* nb = g_hWn + (size_t)g_off[b] * ND + tid * 4;
    __syncthreads();
    int wid = tid >> 5, lane = tid & 31;
    float4 h = *(const float4*)(hb);
    float4 wn = *(const float4*)(nb);
    for (int l = 0; l < len; l++) {
        float4 h2, wn2;
        if (l + 1 < len) {
            h2 = *(const float4*)(hb + (size_t)(l + 1) * ND);
            wn2 = *(const float4*)(nb + (size_t)(l + 1) * ND);
        }
        float p1 = wn.x * tanhf(s4.x) + wn.y * tanhf(s4.y) +
                   wn.z * tanhf(s4.z) + wn.w * tanhf(s4.w);
        float p2 = h.x * w4.x + h.y * w4.y + h.z * w4.z + h.w * w4.w;
#pragma unroll
        for (int off = 16; off > 0; off >>= 1) {
            p1 += __shfl_xor_sync(0xffffffffu, p1, off);
            p2 += __shfl_xor_sync(0xffffffffu, p2, off);
        }
        int buf = l & 1;
        if (lane == 0) { s_red[buf][wid] = p1; s_red[buf][8 + wid] = p2; }
        __syncthreads();
        float nsum = 0.f, cs = 0.f;
#pragma unroll
        for (int i = 0; i < 8; i++) { nsum += s_red[buf][i]; cs += s_red[buf][8 + i]; }
        int ridx = (int)rintf((float)(l + 1) * 9.0f / flen);
        ridx = ridx < 0 ? 0 : (ridx > 9 ? 9 : ridx);
        float pre = cs + s_absp[l] + s_rel[ridx] + bi;
        float x = pre - nsum;
        float prob = 1.f / (1.f + expf(-x));
        if (tid == 0) out[(size_t)b * NL + l] = prob;
        s4.x += prob * h.x; s4.y += prob * h.y;
        s4.z += prob * h.z; s4.w += prob * h.w;
        h = h2; wn = wn2;
    }
    for (int l = len + tid; l < NL; l += 256) out[(size_t)b * NL + l] = 0.f;
}

// ============================================================
extern "C" void kernel_launch(void* const* d_in, const int* in_sizes, int n_in,
                              void* d_out, int out_size) {
    const float* sent      = (const float*)d_in[0];
    const float* fc_w      = (const float*)d_in[1];
    const float* fc_b      = (const float*)d_in[2];
    const float* content_w = (const float*)d_in[3];
    const float* sal_w     = (const float*)d_in[4];
    const float* nov_w     = (const float*)d_in[5];
    const float* abs_emb   = (const float*)d_in[6];
    const float* rel_emb   = (const float*)d_in[7];
    const float* abs_w     = (const float*)d_in[8];
    const float* rel_w     = (const float*)d_in[9];
    const float* bias      = (const float*)d_in[10];
    const int*   lens      = (const int*)d_in[11];
    float* out = (float*)d_out;

    float *docs, *dv, *cwu, *hWn;
    __half *bhi, *blo;
    cudaGetSymbolAddress((void**)&docs, g_docs);
    cudaGetSymbolAddress((void**)&dv,   g_docvec);
    cudaGetSymbolAddress((void**)&cwu,  g_cwu);
    cudaGetSymbolAddress((void**)&hWn,  g_hWn);
    cudaGetSymbolAddress((void**)&bhi,  g_bhi);
    cudaGetSymbolAddress((void**)&blo,  g_blo);

    static cudaStream_t sB = nullptr;
    static cudaEvent_t evFork = nullptr, evJoin = nullptr;
    static bool init_done = false;
    if (!init_done) {
        cudaFuncSetAttribute(k_mma, cudaFuncAttributeMaxDynamicSharedMemorySize, SMEM_BYTES);
        cudaFuncSetAttribute(k_nt_wmma<0>, cudaFuncAttributeMaxDynamicSharedMemorySize, NT_SMEM_BYTES);
        cudaFuncSetAttribute(k_nt_wmma<1>, cudaFuncAttributeMaxDynamicSharedMemorySize, NT_SMEM_BYTES);
        cudaStreamCreateWithFlags(&sB, cudaStreamNonBlocking);
        cudaEventCreateWithFlags(&evFork, cudaEventDisableTiming);
        cudaEventCreateWithFlags(&evJoin, cudaEventDisableTiming);
        init_done = true;
    }

    // ---- fork: branch B (docs -> doc_vec -> cwu, pos) on sB ----
    cudaEventRecord(evFork, 0);
    cudaStreamWaitEvent(sB, evFork, 0);
    k_docs<<<dim3(ND / 256, NB), 256, 0, sB>>>(sent, lens);
    k_pos<<<1, 128, 0, sB>>>(abs_emb, rel_emb, abs_w, rel_w);
    k_nt_wmma<0><<<dim3(ND / 128, NB / 64), 256, NT_SMEM_BYTES, sB>>>(docs, fc_w, fc_b, dv);
    k_nt_wmma<1><<<dim3(ND / 128, NB / 64), 256, NT_SMEM_BYTES, sB>>>(dv, sal_w, content_w, cwu);
    cudaEventRecord(evJoin, sB);

    // ---- branch A: prefix -> splitB -> k_mma (no splitA; A split in-kernel) ----
    k_prefix<<<1, NB>>>(lens);
    k_splitB<<<(ND * ND / 4) / 256, 256>>>(nov_w, bhi, blo);
    k_mma<<<dim3(ND / BN, M_TOTAL / BM), 256, SMEM_BYTES>>>(sent, bhi, blo, hWn);

    // ---- join, then scan ----
    cudaStreamWaitEvent(0, evJoin, 0);
    k_scan<<<NB, 256>>>(sent, lens, bias, out);
}